// round 1
// baseline (speedup 1.0000x reference)
#include <cuda_runtime.h>
#include <math.h>

// TGN growth head, fused: gather + time-encode + concat + Linear(472,128)+ReLU + Linear(128,1)
// Strategy: block = 64 edges x 128 hidden, X tile staged in shared, W double-buffered
// from L2 (w1 = 241KB, fully L2-resident), packed fp32x2 FMA inner loop, fused epilogue.

namespace {
constexpr int MEM_DIM  = 100;
constexpr int TIME_DIM = 100;
constexpr int EDGE_DIM = 172;
constexpr int IN_DIM   = 472;   // 100+100+100+172
constexpr int HID      = 128;
constexpr int TILE_M   = 64;
constexpr int NTHR     = 256;
constexpr int KC       = 8;
constexpr int NCHUNK   = IN_DIM / KC;   // 59
constexpr int XS_STRIDE = 481;          // odd-ish stride: ty-groups land on distinct banks
constexpr int SMEM_FLOATS = TILE_M * XS_STRIDE   // X tile
                          + 2 * KC * HID          // W double buffer
                          + 2 * TIME_DIM          // time_w, time_b
                          + 2 * HID;              // b1, w2
}

typedef unsigned long long ull;

__device__ __forceinline__ void fma2(ull& d, ull a, ull b) {
    // packed fp32x2 FMA (sm_103a; PTX-only form)
    asm("fma.rn.f32x2 %0, %1, %2, %0;" : "+l"(d) : "l"(a), "l"(b));
}

__global__ __launch_bounds__(NTHR, 1)
void tgn_fused(const int* __restrict__ src, const int* __restrict__ dst,
               const float* __restrict__ t, const float* __restrict__ edge_attr,
               const float* __restrict__ memory, const float* __restrict__ last_update,
               const float* __restrict__ time_w, const float* __restrict__ time_b,
               const float* __restrict__ w1, const float* __restrict__ b1,
               const float* __restrict__ w2, const float* __restrict__ b2,
               float* __restrict__ out, int E)
{
    extern __shared__ float smem[];
    float* Xs  = smem;                          // [64][481]
    float* Ws  = Xs + TILE_M * XS_STRIDE;       // [2][KC][128]
    float* sTW = Ws + 2 * KC * HID;             // [100]
    float* sTB = sTW + TIME_DIM;                // [100]
    float* sB1 = sTB + TIME_DIM;                // [128]
    float* sW2 = sB1 + HID;                     // [128]

    const int tid = threadIdx.x;
    const int e0  = blockIdx.x * TILE_M;

    if (tid < TIME_DIM) { sTW[tid] = time_w[tid]; sTB[tid] = time_b[tid]; }
    if (tid >= 128)     { int j = tid - 128; sB1[j] = b1[j]; sW2[j] = w2[j]; }
    __syncthreads();   // sTW/sTB needed by the build phase below

    // ---- prefetch W chunk 0 into buffer 0 (one float4 per thread) ----
    const int kw = tid >> 5;        // 0..7 : k-row within chunk
    const int c4 = tid & 31;        // 0..31: float4 column
    {
        float4 v = *reinterpret_cast<const float4*>(w1 + (size_t)kw * HID + c4 * 4);
        float* d = Ws + kw * HID + c4 * 4;
        d[0] = v.x; d[1] = v.y; d[2] = v.z; d[3] = v.w;
    }

    // ---- build X tile: 8 threads per row, 32 rows per pass, 2 passes ----
    {
        const int l8 = tid & 7;
        for (int rr = tid >> 3; rr < TILE_M; rr += NTHR / 8) {
            const int e = e0 + rr;
            float* xrow = Xs + rr * XS_STRIDE;
            if (e < E) {
                const int   s  = src[e];
                const int   d  = dst[e];
                const float dt = t[e] - last_update[s];
                const float4* ms = reinterpret_cast<const float4*>(memory + (size_t)s * MEM_DIM);
                const float4* md = reinterpret_cast<const float4*>(memory + (size_t)d * MEM_DIM);
                for (int i = l8; i < MEM_DIM / 4; i += 8) {       // 25 float4
                    float4 a = __ldg(ms + i);
                    xrow[i*4+0] = a.x; xrow[i*4+1] = a.y; xrow[i*4+2] = a.z; xrow[i*4+3] = a.w;
                    float4 b = __ldg(md + i);
                    xrow[100+i*4+0] = b.x; xrow[100+i*4+1] = b.y; xrow[100+i*4+2] = b.z; xrow[100+i*4+3] = b.w;
                }
                for (int c = l8; c < TIME_DIM; c += 8)
                    xrow[200 + c] = cosf(fmaf(dt, sTW[c], sTB[c]));
                const float4* ea = reinterpret_cast<const float4*>(edge_attr + (size_t)e * EDGE_DIM);
                for (int i = l8; i < EDGE_DIM / 4; i += 8) {      // 43 float4
                    float4 a = __ldg(ea + i);
                    xrow[300+i*4+0] = a.x; xrow[300+i*4+1] = a.y; xrow[300+i*4+2] = a.z; xrow[300+i*4+3] = a.w;
                }
            } else {
                for (int c = l8; c < IN_DIM; c += 8) xrow[c] = 0.f;
            }
        }
    }
    __syncthreads();   // X tile + W chunk 0 ready

    // ---- GEMM: thread (ty,tx): rows ty*4+tr, cols tx*2 + p*32 (+0/+1) ----
    const int tx = tid & 15;
    const int ty = tid >> 4;

    ull acc[4][4];
    #pragma unroll
    for (int a = 0; a < 4; a++)
        #pragma unroll
        for (int b = 0; b < 4; b++) acc[a][b] = 0ull;

    for (int kc = 0; kc < NCHUNK; ++kc) {
        const int buf = kc & 1;
        const bool pf = (kc + 1 < NCHUNK);
        float4 v;
        if (pf)  // register-prefetch next chunk: latency hidden by compute below
            v = *reinterpret_cast<const float4*>(
                    w1 + ((size_t)(kc + 1) * KC + kw) * HID + c4 * 4);

        const float* wb = Ws + buf * KC * HID;
        const float* xb = Xs + (ty * 4) * XS_STRIDE + kc * KC;
        #pragma unroll
        for (int k = 0; k < KC; ++k) {
            const float* wr = wb + k * HID + tx * 2;   // stride-32 column groups: conflict-free LDS.64
            ull wv0 = *reinterpret_cast<const ull*>(wr);
            ull wv1 = *reinterpret_cast<const ull*>(wr + 32);
            ull wv2 = *reinterpret_cast<const ull*>(wr + 64);
            ull wv3 = *reinterpret_cast<const ull*>(wr + 96);
            #pragma unroll
            for (int tr = 0; tr < 4; ++tr) {
                float x = xb[tr * XS_STRIDE + k];
                ull xx;
                asm("mov.b64 %0, {%1, %1};" : "=l"(xx) : "r"(__float_as_uint(x)));
                fma2(acc[tr][0], xx, wv0);
                fma2(acc[tr][1], xx, wv1);
                fma2(acc[tr][2], xx, wv2);
                fma2(acc[tr][3], xx, wv3);
            }
        }
        if (pf) {   // store prefetched chunk into the other buffer
            float* d = Ws + ((buf ^ 1) * KC + kw) * HID + c4 * 4;
            d[0] = v.x; d[1] = v.y; d[2] = v.z; d[3] = v.w;
        }
        __syncthreads();
    }

    // ---- fused epilogue: bias + ReLU + dot(w2) + width-16 reduction ----
    const float b2v = __ldg(b2);
    #pragma unroll
    for (int tr = 0; tr < 4; ++tr) {
        float s = 0.f;
        #pragma unroll
        for (int p = 0; p < 4; ++p) {
            unsigned lo, hi;
            asm("mov.b64 {%0, %1}, %2;" : "=r"(lo), "=r"(hi) : "l"(acc[tr][p]));
            const int j = tx * 2 + p * 32;
            float h0 = fmaxf(__uint_as_float(lo) + sB1[j],     0.f);
            float h1 = fmaxf(__uint_as_float(hi) + sB1[j + 1], 0.f);
            s = fmaf(h0, sW2[j],     s);
            s = fmaf(h1, sW2[j + 1], s);
        }
        #pragma unroll
        for (int m = 8; m > 0; m >>= 1)
            s += __shfl_xor_sync(0xffffffffu, s, m, 16);
        if (tx == 0) {
            const int e = e0 + ty * 4 + tr;
            if (e < E) out[e] = s + b2v;
        }
    }
}

extern "C" void kernel_launch(void* const* d_in, const int* in_sizes, int n_in,
                              void* d_out, int out_size)
{
    const int*   src = (const int*)  d_in[0];
    const int*   dst = (const int*)  d_in[1];
    const float* t   = (const float*)d_in[2];
    const float* ea  = (const float*)d_in[3];
    const float* mem = (const float*)d_in[4];
    const float* lu  = (const float*)d_in[5];
    const float* tw  = (const float*)d_in[6];
    const float* tb  = (const float*)d_in[7];
    const float* w1  = (const float*)d_in[8];
    const float* b1  = (const float*)d_in[9];
    const float* w2  = (const float*)d_in[10];
    const float* b2  = (const float*)d_in[11];
    float* out = (float*)d_out;

    const int E = in_sizes[0];
    const int smem_bytes = SMEM_FLOATS * (int)sizeof(float);   // ~133 KB
    cudaFuncSetAttribute(tgn_fused, cudaFuncAttributeMaxDynamicSharedMemorySize, smem_bytes);

    const int grid = (E + TILE_M - 1) / TILE_M;
    tgn_fused<<<grid, NTHR, smem_bytes>>>(src, dst, t, ea, mem, lu, tw, tb,
                                          w1, b1, w2, b2, out, E);
}

// round 2
// speedup vs baseline: 1.5086x; 1.5086x over previous
#include <cuda_runtime.h>
#include <cuda_bf16.h>
#include <math.h>

// TGN growth head, fused, tensor-core version.
// gather + time-encode + concat -> split-bf16 (hi/lo) X tile in smem ->
// mma.sync.m16n8k16 x3 terms (xh*wh + xh*wl + xl*wh) -> fused bias/ReLU/w2-dot epilogue.

namespace {
constexpr int MEM_DIM  = 100;
constexpr int TIME_DIM = 100;
constexpr int EDGE_DIM = 172;
constexpr int IN_DIM   = 472;
constexpr int KPAD     = 480;            // pad to multiple of 16
constexpr int HID      = 128;
constexpr int TILE_M   = 64;
constexpr int NTHR     = 256;
constexpr int NCHUNK   = KPAD / 16;      // 30
constexpr int XSTR     = 488;            // bf16 elems/row: 976B -> LDSM phase conflict-free
constexpr int WSTR     = 136;            // bf16 elems/row: 272B -> LDSM phase conflict-free
constexpr int SMEM_BYTES = 2 * (TILE_M * XSTR * 2)
                         + 2 * (2 * 16 * WSTR * 2)
                         + TILE_M * 4 * 4;
}

__device__ __nv_bfloat16 g_Whi[KPAD * HID];
__device__ __nv_bfloat16 g_Wlo[KPAD * HID];

__global__ void prep_w(const float* __restrict__ w1) {
    int idx = blockIdx.x * blockDim.x + threadIdx.x;
    if (idx >= KPAD * HID) return;
    int k = idx / HID;
    float v = (k < IN_DIM) ? w1[idx] : 0.f;          // w1 is [472][128] row-major
    __nv_bfloat16 h = __float2bfloat16(v);
    g_Whi[idx] = h;
    g_Wlo[idx] = __float2bfloat16(v - __bfloat162float(h));
}

__device__ __forceinline__ void ldsm4(unsigned* r, unsigned addr) {
    asm volatile("ldmatrix.sync.aligned.m8n8.x4.shared.b16 {%0,%1,%2,%3}, [%4];"
                 : "=r"(r[0]), "=r"(r[1]), "=r"(r[2]), "=r"(r[3]) : "r"(addr));
}
__device__ __forceinline__ void ldsm4t(unsigned* r, unsigned addr) {
    asm volatile("ldmatrix.sync.aligned.m8n8.x4.trans.shared.b16 {%0,%1,%2,%3}, [%4];"
                 : "=r"(r[0]), "=r"(r[1]), "=r"(r[2]), "=r"(r[3]) : "r"(addr));
}
__device__ __forceinline__ void mma16816(float* c, const unsigned* a, unsigned b0, unsigned b1) {
    asm volatile("mma.sync.aligned.m16n8k16.row.col.f32.bf16.bf16.f32 "
                 "{%0,%1,%2,%3}, {%4,%5,%6,%7}, {%8,%9}, {%0,%1,%2,%3};"
                 : "+f"(c[0]), "+f"(c[1]), "+f"(c[2]), "+f"(c[3])
                 : "r"(a[0]), "r"(a[1]), "r"(a[2]), "r"(a[3]), "r"(b0), "r"(b1));
}

__device__ __forceinline__ void split2st(__nv_bfloat16* xh, __nv_bfloat16* xl,
                                         int off, float v0, float v1) {
    __nv_bfloat16 h0 = __float2bfloat16(v0);
    __nv_bfloat16 h1 = __float2bfloat16(v1);
    __nv_bfloat16 q0 = __float2bfloat16(v0 - __bfloat162float(h0));
    __nv_bfloat16 q1 = __float2bfloat16(v1 - __bfloat162float(h1));
    __nv_bfloat162 hp; hp.x = h0; hp.y = h1;
    __nv_bfloat162 qp; qp.x = q0; qp.y = q1;
    *reinterpret_cast<__nv_bfloat162*>(xh + off) = hp;
    *reinterpret_cast<__nv_bfloat162*>(xl + off) = qp;
}

__global__ __launch_bounds__(NTHR, 1)
void tgn_mma(const int* __restrict__ src, const int* __restrict__ dst,
             const float* __restrict__ t, const float* __restrict__ edge_attr,
             const float* __restrict__ memory, const float* __restrict__ last_update,
             const float* __restrict__ time_w, const float* __restrict__ time_b,
             const float* __restrict__ b1, const float* __restrict__ w2,
             const float* __restrict__ b2, float* __restrict__ out, int E)
{
    extern __shared__ char smem_raw[];
    __nv_bfloat16* Xhi = reinterpret_cast<__nv_bfloat16*>(smem_raw);
    __nv_bfloat16* Xlo = Xhi + TILE_M * XSTR;
    __nv_bfloat16* Wh  = Xlo + TILE_M * XSTR;     // [2][16][WSTR]
    __nv_bfloat16* Wl  = Wh + 2 * 16 * WSTR;
    float* partial     = reinterpret_cast<float*>(Wl + 2 * 16 * WSTR);  // [64][4]

    const int tid  = threadIdx.x;
    const int e0   = blockIdx.x * TILE_M;
    const int lane = tid & 31;
    const int wid  = tid >> 5;
    const int wm   = wid >> 2;          // 0..1 : 32-row group
    const int wn   = wid & 3;           // 0..3 : 32-col group
    const int g    = lane >> 2;
    const int tig  = lane & 3;

    // ---- preload W chunk 0 into buffer 0 ----
    const int wr = tid >> 4;            // 0..15 : k-row within chunk
    const int wc = (tid & 15) * 8;      // col start (8 bf16 = 16B)
    {
        uint4 vh = *reinterpret_cast<const uint4*>(g_Whi + wr * HID + wc);
        uint4 vl = *reinterpret_cast<const uint4*>(g_Wlo + wr * HID + wc);
        *reinterpret_cast<uint4*>(Wh + wr * WSTR + wc) = vh;
        *reinterpret_cast<uint4*>(Wl + wr * WSTR + wc) = vl;
    }

    // ---- build X tile (hi/lo bf16), 8 threads per row ----
    {
        const int l8 = tid & 7;
        for (int rr = tid >> 3; rr < TILE_M; rr += NTHR / 8) {
            const int e = e0 + rr;
            __nv_bfloat16* xh = Xhi + rr * XSTR;
            __nv_bfloat16* xl = Xlo + rr * XSTR;
            if (e < E) {
                const int   s  = src[e];
                const int   d  = dst[e];
                const float dt = t[e] - last_update[s];
                const float4* ms = reinterpret_cast<const float4*>(memory + (size_t)s * MEM_DIM);
                const float4* md = reinterpret_cast<const float4*>(memory + (size_t)d * MEM_DIM);
                for (int i = l8; i < MEM_DIM / 4; i += 8) {
                    float4 a = __ldg(ms + i);
                    split2st(xh, xl, i * 4,     a.x, a.y);
                    split2st(xh, xl, i * 4 + 2, a.z, a.w);
                    float4 b = __ldg(md + i);
                    split2st(xh, xl, 100 + i * 4,     b.x, b.y);
                    split2st(xh, xl, 100 + i * 4 + 2, b.z, b.w);
                }
                for (int c = l8; c < TIME_DIM; c += 8) {
                    float v = cosf(fmaf(dt, __ldg(time_w + c), __ldg(time_b + c)));
                    __nv_bfloat16 h = __float2bfloat16(v);
                    xh[200 + c] = h;
                    xl[200 + c] = __float2bfloat16(v - __bfloat162float(h));
                }
                const float4* ea = reinterpret_cast<const float4*>(edge_attr + (size_t)e * EDGE_DIM);
                for (int i = l8; i < EDGE_DIM / 4; i += 8) {
                    float4 a = __ldg(ea + i);
                    split2st(xh, xl, 300 + i * 4,     a.x, a.y);
                    split2st(xh, xl, 300 + i * 4 + 2, a.z, a.w);
                }
                xh[472 + l8] = __float2bfloat16(0.f);   // zero pad 472..479
                xl[472 + l8] = __float2bfloat16(0.f);
            } else {
                for (int c = l8; c < KPAD; c += 8) {
                    xh[c] = __float2bfloat16(0.f);
                    xl[c] = __float2bfloat16(0.f);
                }
            }
        }
    }
    __syncthreads();

    // ---- per-thread b1/w2 for the 8 hidden cols this thread owns ----
    float b1v[8], w2v[8];
    #pragma unroll
    for (int nt = 0; nt < 4; ++nt)
        #pragma unroll
        for (int j = 0; j < 2; ++j) {
            int n = wn * 32 + nt * 8 + tig * 2 + j;
            b1v[nt * 2 + j] = __ldg(b1 + n);
            w2v[nt * 2 + j] = __ldg(w2 + n);
        }

    // ---- LDSM address bases ----
    // A (no trans): lanes 0-15 -> rows m0+(lane&15), k+0 ; lanes 16-31 -> rows m0+(lane-16), k+8
    const int arow  = lane & 15;
    const int akoff = (lane >> 4) * 8;
    unsigned aHi0 = (unsigned)__cvta_generic_to_shared(Xhi + (wm * 32 + arow) * XSTR + akoff);
    unsigned aHi1 = (unsigned)__cvta_generic_to_shared(Xhi + (wm * 32 + 16 + arow) * XSTR + akoff);
    unsigned aLo0 = (unsigned)__cvta_generic_to_shared(Xlo + (wm * 32 + arow) * XSTR + akoff);
    unsigned aLo1 = (unsigned)__cvta_generic_to_shared(Xlo + (wm * 32 + 16 + arow) * XSTR + akoff);
    // B (trans): lanes 0-15 -> k rows 0..15 at col base; lanes 16-31 -> same k rows, +8 cols.
    // Pair 0 covers cols [wn*32, wn*32+16), pair 1 covers cols [wn*32+16, wn*32+32).
    const int bkr  = lane & 15;
    const int bnc0 = wn * 32 + (lane >> 4) * 8;
    const int bnc1 = wn * 32 + 16 + (lane >> 4) * 8;
    unsigned bHi0 = (unsigned)__cvta_generic_to_shared(Wh + bkr * WSTR + bnc0);
    unsigned bHi1 = (unsigned)__cvta_generic_to_shared(Wh + bkr * WSTR + bnc1);
    unsigned bLo0 = (unsigned)__cvta_generic_to_shared(Wl + bkr * WSTR + bnc0);
    unsigned bLo1 = (unsigned)__cvta_generic_to_shared(Wl + bkr * WSTR + bnc1);
    const unsigned wBufBytes = 16 * WSTR * 2;

    float acc[2][4][4];
    #pragma unroll
    for (int a = 0; a < 2; a++)
        #pragma unroll
        for (int b = 0; b < 4; b++)
            #pragma unroll
            for (int c = 0; c < 4; c++) acc[a][b][c] = 0.f;

    for (int kc = 0; kc < NCHUNK; ++kc) {
        const int buf = kc & 1;
        const bool pf = (kc + 1 < NCHUNK);
        uint4 vh, vl;
        if (pf) {
            vh = *reinterpret_cast<const uint4*>(g_Whi + ((kc + 1) * 16 + wr) * HID + wc);
            vl = *reinterpret_cast<const uint4*>(g_Wlo + ((kc + 1) * 16 + wr) * HID + wc);
        }

        const unsigned kByte = (unsigned)(kc * 16 * 2);
        unsigned ah0[4], ah1[4], al0[4], al1[4];
        ldsm4(ah0, aHi0 + kByte);
        ldsm4(ah1, aHi1 + kByte);
        ldsm4(al0, aLo0 + kByte);
        ldsm4(al1, aLo1 + kByte);

        const unsigned wOff = buf ? wBufBytes : 0u;
        unsigned bh0[4], bh1[4], bl0[4], bl1[4];
        ldsm4t(bh0, bHi0 + wOff);
        ldsm4t(bh1, bHi1 + wOff);
        ldsm4t(bl0, bLo0 + wOff);
        ldsm4t(bl1, bLo1 + wOff);

        #pragma unroll
        for (int mt = 0; mt < 2; ++mt) {
            const unsigned* ah = mt ? ah1 : ah0;
            const unsigned* al = mt ? al1 : al0;
            #pragma unroll
            for (int nt = 0; nt < 4; ++nt) {
                const unsigned* bh = (nt < 2) ? bh0 : bh1;
                const unsigned* bl = (nt < 2) ? bl0 : bl1;
                const int p = (nt & 1) * 2;
                mma16816(acc[mt][nt], ah, bh[p], bh[p + 1]);
                mma16816(acc[mt][nt], ah, bl[p], bl[p + 1]);
                mma16816(acc[mt][nt], al, bh[p], bh[p + 1]);
            }
        }

        if (pf) {
            *reinterpret_cast<uint4*>(Wh + ((buf ^ 1) * 16 + wr) * WSTR + wc) = vh;
            *reinterpret_cast<uint4*>(Wl + ((buf ^ 1) * 16 + wr) * WSTR + wc) = vl;
        }
        __syncthreads();
    }

    // ---- fused epilogue: bias + ReLU + dot(w2), quad shuffle + smem cross-warp reduce ----
    #pragma unroll
    for (int mt = 0; mt < 2; ++mt) {
        float sA = 0.f, sB = 0.f;
        #pragma unroll
        for (int nt = 0; nt < 4; ++nt) {
            float h0 = fmaxf(acc[mt][nt][0] + b1v[nt * 2 + 0], 0.f);
            float h1 = fmaxf(acc[mt][nt][1] + b1v[nt * 2 + 1], 0.f);
            float h2 = fmaxf(acc[mt][nt][2] + b1v[nt * 2 + 0], 0.f);
            float h3 = fmaxf(acc[mt][nt][3] + b1v[nt * 2 + 1], 0.f);
            sA = fmaf(h0, w2v[nt * 2 + 0], sA);
            sA = fmaf(h1, w2v[nt * 2 + 1], sA);
            sB = fmaf(h2, w2v[nt * 2 + 0], sB);
            sB = fmaf(h3, w2v[nt * 2 + 1], sB);
        }
        sA += __shfl_xor_sync(0xffffffffu, sA, 1);
        sA += __shfl_xor_sync(0xffffffffu, sA, 2);
        sB += __shfl_xor_sync(0xffffffffu, sB, 1);
        sB += __shfl_xor_sync(0xffffffffu, sB, 2);
        if (tig == 0) {
            const int rA = wm * 32 + mt * 16 + g;
            partial[rA * 4 + wn] = sA;
            partial[(rA + 8) * 4 + wn] = sB;
        }
    }
    __syncthreads();

    if (tid < TILE_M) {
        const int e = e0 + tid;
        if (e < E) {
            float s = partial[tid * 4 + 0] + partial[tid * 4 + 1]
                    + partial[tid * 4 + 2] + partial[tid * 4 + 3];
            out[e] = s + __ldg(b2);
        }
    }
}

extern "C" void kernel_launch(void* const* d_in, const int* in_sizes, int n_in,
                              void* d_out, int out_size)
{
    const int*   src = (const int*)  d_in[0];
    const int*   dst = (const int*)  d_in[1];
    const float* t   = (const float*)d_in[2];
    const float* ea  = (const float*)d_in[3];
    const float* mem = (const float*)d_in[4];
    const float* lu  = (const float*)d_in[5];
    const float* tw  = (const float*)d_in[6];
    const float* tb  = (const float*)d_in[7];
    const float* w1  = (const float*)d_in[8];
    const float* b1  = (const float*)d_in[9];
    const float* w2  = (const float*)d_in[10];
    const float* b2  = (const float*)d_in[11];
    float* out = (float*)d_out;

    const int E = in_sizes[0];

    prep_w<<<(KPAD * HID + 255) / 256, 256>>>(w1);

    cudaFuncSetAttribute(tgn_mma, cudaFuncAttributeMaxDynamicSharedMemorySize, SMEM_BYTES);
    const int grid = (E + TILE_M - 1) / TILE_M;
    tgn_mma<<<grid, NTHR, SMEM_BYTES>>>(src, dst, t, ea, mem, lu, tw, tb,
                                        b1, w2, b2, out, E);
}

// round 3
// speedup vs baseline: 2.1134x; 1.4009x over previous
#include <cuda_runtime.h>
#include <cuda_bf16.h>
#include <math.h>

// TGN growth head, fused, tensor-core (split-bf16 3-term) version, round 3:
// TILE_M=32 + 2 CTAs/SM so gather/build overlaps MMA; W staged 32 k-rows per sync.

namespace {
constexpr int MEM_DIM  = 100;
constexpr int TIME_DIM = 100;
constexpr int EDGE_DIM = 172;
constexpr int IN_DIM   = 472;
constexpr int KPAD     = 480;            // 15 stages of 32
constexpr int HID      = 128;
constexpr int TILE_M   = 32;
constexpr int NTHR     = 256;
constexpr int KSTAGE   = 32;             // k-rows per smem stage (2 sub-chunks of 16)
constexpr int NSTAGE   = KPAD / KSTAGE;  // 15
constexpr int XSTR     = 488;            // bf16/row -> LDSM conflict-free
constexpr int WSTR     = 136;            // bf16/row -> LDSM conflict-free
constexpr int SMEM_BYTES = 2 * (TILE_M * XSTR * 2)        // Xhi, Xlo
                         + 2 * (2 * KSTAGE * WSTR * 2)    // Wh, Wl double-buffered
                         + TILE_M * 4 * 4;                // partial
}

__device__ __nv_bfloat16 g_Whi[KPAD * HID];
__device__ __nv_bfloat16 g_Wlo[KPAD * HID];

__global__ void prep_w(const float* __restrict__ w1) {
    int idx = blockIdx.x * blockDim.x + threadIdx.x;
    if (idx >= KPAD * HID) return;
    int k = idx / HID;
    float v = (k < IN_DIM) ? w1[idx] : 0.f;          // w1 row-major [472][128]
    __nv_bfloat16 h = __float2bfloat16(v);
    g_Whi[idx] = h;
    g_Wlo[idx] = __float2bfloat16(v - __bfloat162float(h));
}

__device__ __forceinline__ void ldsm4(unsigned* r, unsigned addr) {
    asm volatile("ldmatrix.sync.aligned.m8n8.x4.shared.b16 {%0,%1,%2,%3}, [%4];"
                 : "=r"(r[0]), "=r"(r[1]), "=r"(r[2]), "=r"(r[3]) : "r"(addr));
}
__device__ __forceinline__ void ldsm4t(unsigned* r, unsigned addr) {
    asm volatile("ldmatrix.sync.aligned.m8n8.x4.trans.shared.b16 {%0,%1,%2,%3}, [%4];"
                 : "=r"(r[0]), "=r"(r[1]), "=r"(r[2]), "=r"(r[3]) : "r"(addr));
}
__device__ __forceinline__ void mma16816(float* c, const unsigned* a, unsigned b0, unsigned b1) {
    asm volatile("mma.sync.aligned.m16n8k16.row.col.f32.bf16.bf16.f32 "
                 "{%0,%1,%2,%3}, {%4,%5,%6,%7}, {%8,%9}, {%0,%1,%2,%3};"
                 : "+f"(c[0]), "+f"(c[1]), "+f"(c[2]), "+f"(c[3])
                 : "r"(a[0]), "r"(a[1]), "r"(a[2]), "r"(a[3]), "r"(b0), "r"(b1));
}

__device__ __forceinline__ void split2st(__nv_bfloat16* xh, __nv_bfloat16* xl,
                                         int off, float v0, float v1) {
    __nv_bfloat16 h0 = __float2bfloat16(v0);
    __nv_bfloat16 h1 = __float2bfloat16(v1);
    __nv_bfloat16 q0 = __float2bfloat16(v0 - __bfloat162float(h0));
    __nv_bfloat16 q1 = __float2bfloat16(v1 - __bfloat162float(h1));
    __nv_bfloat162 hp; hp.x = h0; hp.y = h1;
    __nv_bfloat162 qp; qp.x = q0; qp.y = q1;
    *reinterpret_cast<__nv_bfloat162*>(xh + off) = hp;
    *reinterpret_cast<__nv_bfloat162*>(xl + off) = qp;
}

__global__ __launch_bounds__(NTHR, 2)
void tgn_mma(const int* __restrict__ src, const int* __restrict__ dst,
             const float* __restrict__ t, const float* __restrict__ edge_attr,
             const float* __restrict__ memory, const float* __restrict__ last_update,
             const float* __restrict__ time_w, const float* __restrict__ time_b,
             const float* __restrict__ b1, const float* __restrict__ w2,
             const float* __restrict__ b2, float* __restrict__ out, int E)
{
    extern __shared__ char smem_raw[];
    __nv_bfloat16* Xhi = reinterpret_cast<__nv_bfloat16*>(smem_raw);
    __nv_bfloat16* Xlo = Xhi + TILE_M * XSTR;
    __nv_bfloat16* Wh  = Xlo + TILE_M * XSTR;     // [2][KSTAGE][WSTR]
    __nv_bfloat16* Wl  = Wh + 2 * KSTAGE * WSTR;
    float* partial     = reinterpret_cast<float*>(Wl + 2 * KSTAGE * WSTR);  // [32][4]

    const int tid  = threadIdx.x;
    const int e0   = blockIdx.x * TILE_M;
    const int lane = tid & 31;
    const int wid  = tid >> 5;
    const int wm   = wid >> 2;          // 0..1 : 16-row tile
    const int wn   = wid & 3;           // 0..3 : 32-col group
    const int g    = lane >> 2;
    const int tig  = lane & 3;

    // ---- preload W stage 0 (32 k-rows): each thread 2 rows x 8 cols ----
    const int wr = tid >> 4;            // 0..15
    const int wc = (tid & 15) * 8;
    {
        *reinterpret_cast<uint4*>(Wh + wr * WSTR + wc) =
            *reinterpret_cast<const uint4*>(g_Whi + wr * HID + wc);
        *reinterpret_cast<uint4*>(Wh + (wr + 16) * WSTR + wc) =
            *reinterpret_cast<const uint4*>(g_Whi + (wr + 16) * HID + wc);
        *reinterpret_cast<uint4*>(Wl + wr * WSTR + wc) =
            *reinterpret_cast<const uint4*>(g_Wlo + wr * HID + wc);
        *reinterpret_cast<uint4*>(Wl + (wr + 16) * WSTR + wc) =
            *reinterpret_cast<const uint4*>(g_Wlo + (wr + 16) * HID + wc);
    }

    // ---- build X tile (hi/lo bf16), 8 threads per row, 32 rows ----
    {
        const int l8 = tid & 7;
        const int rr = tid >> 3;        // 0..31
        const int e  = e0 + rr;
        __nv_bfloat16* xh = Xhi + rr * XSTR;
        __nv_bfloat16* xl = Xlo + rr * XSTR;
        if (e < E) {
            const int   s  = src[e];
            const int   d  = dst[e];
            const float dt = t[e] - last_update[s];
            const float4* ms = reinterpret_cast<const float4*>(memory + (size_t)s * MEM_DIM);
            const float4* md = reinterpret_cast<const float4*>(memory + (size_t)d * MEM_DIM);
            for (int i = l8; i < MEM_DIM / 4; i += 8) {
                float4 a = __ldg(ms + i);
                split2st(xh, xl, i * 4,     a.x, a.y);
                split2st(xh, xl, i * 4 + 2, a.z, a.w);
                float4 b = __ldg(md + i);
                split2st(xh, xl, 100 + i * 4,     b.x, b.y);
                split2st(xh, xl, 100 + i * 4 + 2, b.z, b.w);
            }
            for (int c = l8; c < TIME_DIM; c += 8) {
                float v = cosf(fmaf(dt, __ldg(time_w + c), __ldg(time_b + c)));
                __nv_bfloat16 h = __float2bfloat16(v);
                xh[200 + c] = h;
                xl[200 + c] = __float2bfloat16(v - __bfloat162float(h));
            }
            const float4* ea = reinterpret_cast<const float4*>(edge_attr + (size_t)e * EDGE_DIM);
            for (int i = l8; i < EDGE_DIM / 4; i += 8) {
                float4 a = __ldg(ea + i);
                split2st(xh, xl, 300 + i * 4,     a.x, a.y);
                split2st(xh, xl, 300 + i * 4 + 2, a.z, a.w);
            }
            xh[472 + l8] = __float2bfloat16(0.f);   // zero pad 472..479
            xl[472 + l8] = __float2bfloat16(0.f);
        } else {
            for (int c = l8; c < KPAD; c += 8) {
                xh[c] = __float2bfloat16(0.f);
                xl[c] = __float2bfloat16(0.f);
            }
        }
    }
    __syncthreads();

    // ---- per-thread b1/w2 for the 8 hidden cols this thread owns ----
    float b1v[8], w2v[8];
    #pragma unroll
    for (int nt = 0; nt < 4; ++nt)
        #pragma unroll
        for (int j = 0; j < 2; ++j) {
            int n = wn * 32 + nt * 8 + tig * 2 + j;
            b1v[nt * 2 + j] = __ldg(b1 + n);
            w2v[nt * 2 + j] = __ldg(w2 + n);
        }

    // ---- LDSM address bases ----
    const int arow  = lane & 15;
    const int akoff = (lane >> 4) * 8;
    unsigned aHi = (unsigned)__cvta_generic_to_shared(Xhi + (wm * 16 + arow) * XSTR + akoff);
    unsigned aLo = (unsigned)__cvta_generic_to_shared(Xlo + (wm * 16 + arow) * XSTR + akoff);
    const int bkr  = lane & 15;
    const int bnc0 = wn * 32 + (lane >> 4) * 8;
    const int bnc1 = wn * 32 + 16 + (lane >> 4) * 8;
    unsigned bHi0 = (unsigned)__cvta_generic_to_shared(Wh + bkr * WSTR + bnc0);
    unsigned bHi1 = (unsigned)__cvta_generic_to_shared(Wh + bkr * WSTR + bnc1);
    unsigned bLo0 = (unsigned)__cvta_generic_to_shared(Wl + bkr * WSTR + bnc0);
    unsigned bLo1 = (unsigned)__cvta_generic_to_shared(Wl + bkr * WSTR + bnc1);
    const unsigned wBufBytes = KSTAGE * WSTR * 2;
    const unsigned wSubBytes = 16 * WSTR * 2;     // sub-chunk k-offset inside stage

    float acc[4][4];
    #pragma unroll
    for (int b = 0; b < 4; b++)
        #pragma unroll
        for (int c = 0; c < 4; c++) acc[b][c] = 0.f;

    for (int s = 0; s < NSTAGE; ++s) {
        const int buf = s & 1;
        const bool pf = (s + 1 < NSTAGE);
        uint4 vh0, vh1, vl0, vl1;
        if (pf) {
            const int r0 = (s + 1) * KSTAGE + wr;
            vh0 = *reinterpret_cast<const uint4*>(g_Whi + r0 * HID + wc);
            vh1 = *reinterpret_cast<const uint4*>(g_Whi + (r0 + 16) * HID + wc);
            vl0 = *reinterpret_cast<const uint4*>(g_Wlo + r0 * HID + wc);
            vl1 = *reinterpret_cast<const uint4*>(g_Wlo + (r0 + 16) * HID + wc);
        }

        const unsigned wOff = buf ? wBufBytes : 0u;
        #pragma unroll
        for (int j = 0; j < 2; ++j) {
            const unsigned kByte = (unsigned)((s * KSTAGE + j * 16) * 2);
            unsigned ah[4], al[4];
            ldsm4(ah, aHi + kByte);
            ldsm4(al, aLo + kByte);
            const unsigned bo = wOff + j * wSubBytes;
            unsigned bh0[4], bh1[4], bl0[4], bl1[4];
            ldsm4t(bh0, bHi0 + bo);
            ldsm4t(bh1, bHi1 + bo);
            ldsm4t(bl0, bLo0 + bo);
            ldsm4t(bl1, bLo1 + bo);

            #pragma unroll
            for (int nt = 0; nt < 4; ++nt) {
                const unsigned* bh = (nt < 2) ? bh0 : bh1;
                const unsigned* bl = (nt < 2) ? bl0 : bl1;
                const int p = (nt & 1) * 2;
                mma16816(acc[nt], ah, bh[p], bh[p + 1]);
                mma16816(acc[nt], ah, bl[p], bl[p + 1]);
                mma16816(acc[nt], al, bh[p], bh[p + 1]);
            }
        }

        if (pf) {
            const int d0 = (buf ^ 1) * KSTAGE + wr;
            *reinterpret_cast<uint4*>(Wh + d0 * WSTR + wc) = vh0;
            *reinterpret_cast<uint4*>(Wh + (d0 + 16) * WSTR + wc) = vh1;
            *reinterpret_cast<uint4*>(Wl + d0 * WSTR + wc) = vl0;
            *reinterpret_cast<uint4*>(Wl + (d0 + 16) * WSTR + wc) = vl1;
        }
        __syncthreads();
    }

    // ---- fused epilogue: bias + ReLU + dot(w2), quad shuffle + smem cross-warp reduce ----
    {
        float sA = 0.f, sB = 0.f;    // rows wm*16+g and wm*16+g+8
        #pragma unroll
        for (int nt = 0; nt < 4; ++nt) {
            float h0 = fmaxf(acc[nt][0] + b1v[nt * 2 + 0], 0.f);
            float h1 = fmaxf(acc[nt][1] + b1v[nt * 2 + 1], 0.f);
            float h2 = fmaxf(acc[nt][2] + b1v[nt * 2 + 0], 0.f);
            float h3 = fmaxf(acc[nt][3] + b1v[nt * 2 + 1], 0.f);
            sA = fmaf(h0, w2v[nt * 2 + 0], sA);
            sA = fmaf(h1, w2v[nt * 2 + 1], sA);
            sB = fmaf(h2, w2v[nt * 2 + 0], sB);
            sB = fmaf(h3, w2v[nt * 2 + 1], sB);
        }
        sA += __shfl_xor_sync(0xffffffffu, sA, 1);
        sA += __shfl_xor_sync(0xffffffffu, sA, 2);
        sB += __shfl_xor_sync(0xffffffffu, sB, 1);
        sB += __shfl_xor_sync(0xffffffffu, sB, 2);
        if (tig == 0) {
            const int rA = wm * 16 + g;
            partial[rA * 4 + wn] = sA;
            partial[(rA + 8) * 4 + wn] = sB;
        }
    }
    __syncthreads();

    if (tid < TILE_M) {
        const int e = e0 + tid;
        if (e < E) {
            float s = partial[tid * 4 + 0] + partial[tid * 4 + 1]
                    + partial[tid * 4 + 2] + partial[tid * 4 + 3];
            out[e] = s + __ldg(b2);
        }
    }
}

extern "C" void kernel_launch(void* const* d_in, const int* in_sizes, int n_in,
                              void* d_out, int out_size)
{
    const int*   src = (const int*)  d_in[0];
    const int*   dst = (const int*)  d_in[1];
    const float* t   = (const float*)d_in[2];
    const float* ea  = (const float*)d_in[3];
    const float* mem = (const float*)d_in[4];
    const float* lu  = (const float*)d_in[5];
    const float* tw  = (const float*)d_in[6];
    const float* tb  = (const float*)d_in[7];
    const float* w1  = (const float*)d_in[8];
    const float* b1  = (const float*)d_in[9];
    const float* w2  = (const float*)d_in[10];
    const float* b2  = (const float*)d_in[11];
    float* out = (float*)d_out;

    const int E = in_sizes[0];

    prep_w<<<(KPAD * HID + 255) / 256, 256>>>(w1);

    cudaFuncSetAttribute(tgn_mma, cudaFuncAttributeMaxDynamicSharedMemorySize, SMEM_BYTES);
    const int grid = (E + TILE_M - 1) / TILE_M;
    tgn_mma<<<grid, NTHR, SMEM_BYTES>>>(src, dst, t, ea, mem, lu, tw, tb,
                                        b1, w2, b2, out, E);
}